// round 10
// baseline (speedup 1.0000x reference)
#include <cuda_runtime.h>
#include <cuda_fp16.h>
#include <cstdint>

#define BSZ 8
#define CH  64
#define H   256
#define W   256
#define HW  (H*W)
#define EPS 1e-5f
#define SLOPE 0.01f
#define CROP 244
#define CSPL 0.03125f   // c = 2^-5 split-compensation constant

typedef unsigned long long u64;

#define FMA2(d,a,b,c) asm("fma.rn.f32x2 %0, %1, %2, %3;" : "=l"(d) : "l"(a), "l"(b), "l"(c))
#define PACK2(d,lo,hi) asm("mov.b64 %0, {%1, %2};" : "=l"(d) : "f"(lo), "f"(hi))
#define UNPK2(lo,hi,d) asm("mov.b64 {%0, %1}, %2;" : "=f"(lo), "=f"(hi) : "l"(d))

__device__ __forceinline__ uint32_t smem_u32(const void* p) {
    uint32_t a;
    asm("{ .reg .u64 t; cvta.to.shared.u64 t, %1; cvt.u32.u64 %0, t; }" : "=r"(a) : "l"(p));
    return a;
}
__device__ __forceinline__ void ldsm4(uint32_t* r, uint32_t addr) {
    asm volatile("ldmatrix.sync.aligned.m8n8.x4.shared.b16 {%0,%1,%2,%3}, [%4];"
                 : "=r"(r[0]), "=r"(r[1]), "=r"(r[2]), "=r"(r[3]) : "r"(addr));
}
__device__ __forceinline__ void mma16816h(float* d, const uint32_t* a, const uint32_t* b) {
    asm volatile("mma.sync.aligned.m16n8k16.row.col.f32.f16.f16.f32 "
                 "{%0,%1,%2,%3}, {%4,%5,%6,%7}, {%8,%9}, {%0,%1,%2,%3};"
                 : "+f"(d[0]), "+f"(d[1]), "+f"(d[2]), "+f"(d[3])
                 : "r"(a[0]), "r"(a[1]), "r"(a[2]), "r"(a[3]), "r"(b[0]), "r"(b[1]));
}

// ---------------- scratch ----------------
__device__ float g_actA[BSZ*CH*HW];
__device__ float g_actB[BSZ*CH*HW];
__device__ float g_stats[8*BSZ*CH*2];
__device__ float g_norm[8*BSZ*CH*2];
__device__ float g_loss_sb[169*BSZ];
// fragment-ordered weights: [layer][tap][ks][n8grp][lane] = uint4{bh_klo, bh_khi, b2_klo, b2_khi}
__device__ uint4 g_wprep[7*9*1024];

__global__ void zero_stats_kernel() {
    for (int i = threadIdx.x; i < 8*BSZ*CH*2; i += blockDim.x) g_stats[i] = 0.f;
}

static __device__ __forceinline__ uint32_t h2u(__half a, __half b) {
    __half2 p = __halves2half2(a, b);
    return *(uint32_t*)&p;
}

// ---------------- weight prep: fragment-order pack (wh + compensated w2) ----------------
__global__ void wprep_kernel(const float* __restrict__ ws) {
    const int t = blockIdx.x;    // tap 0..8
    const int l = blockIdx.y;    // layer 0..6
    const float* wb = ws + (size_t)l*64*64*9;
    uint4* dst = g_wprep + (size_t)(l*9 + t)*1024;
    for (int u = threadIdx.x; u < 1024; u += blockDim.x) {
        const int ks = u >> 8;
        const int g  = (u >> 5) & 7;
        const int ln = u & 31;
        const int co = g*8 + (ln >> 2);
        const int k0 = ks*16 + 2*(ln & 3);
        float w[4];
        w[0] = wb[((size_t)co*64 + k0    )*9 + t];
        w[1] = wb[((size_t)co*64 + k0 + 1)*9 + t];
        w[2] = wb[((size_t)co*64 + k0 + 8)*9 + t];
        w[3] = wb[((size_t)co*64 + k0 + 9)*9 + t];
        __half hh[4], cc[4];
        #pragma unroll
        for (int i = 0; i < 4; i++) {
            hh[i] = __float2half_rn(w[i]);
            float whf = __half2float(hh[i]);
            cc[i] = __float2half_rn(whf + 32.0f*(w[i] - whf));   // wh + wl/c
        }
        uint4 v;
        v.x = h2u(hh[0], hh[1]);
        v.y = h2u(hh[2], hh[3]);
        v.z = h2u(cc[0], cc[1]);
        v.w = h2u(cc[2], cc[3]);
        dst[u] = v;
    }
}

// ---------------- HMMA conv layer (compensated fp16 2-pass, B via LDG.128) ----------------
// smem: window xh [204*128B], window a2 [204*128B], nrm [512B]
#define OF_WHI 0
#define OF_WLO 26112
#define OF_NRM 52224
#define SMEM_MMA 52736

__global__ void __launch_bounds__(256, 2)
mma_conv_kernel(const float* __restrict__ in,
                const uint4* __restrict__ wp,           // this layer: [9][1024] frag-order
                const float* __restrict__ bias,
                const float* __restrict__ nrm,          // [BSZ*64*2] (mean,rstd)
                float* __restrict__ out,
                float* __restrict__ statacc)            // [BSZ*64*2]
{
    extern __shared__ char smem[];
    const uint32_t sb = smem_u32(smem);
    const int tid = threadIdx.x;
    const int wid = tid >> 5, lane = tid & 31;
    const int tileW = blockIdx.x;   // 0..7
    const int tileH = blockIdx.y;   // 0..63
    const int b = blockIdx.z;

    if (tid < 64)
        *(float2*)(smem + OF_NRM + tid*8) = ((const float2*)nrm)[b*64 + tid];
    __syncthreads();   // nrm visible to ALL warps before window fill reads it

    // ---- window fill: 204 rows x 64 ci over ALL 256 threads ----
    for (int g = tid; g < 1632; g += 256) {
        const int chunk = g / 204;
        const int r = g - chunk*204;
        const int rr = r / 34, cc = r - rr*34;
        int gh = tileH*4 - 1 + rr; gh = gh < 0 ? 0 : (gh > H-1 ? H-1 : gh);
        int gw = tileW*32 - 1 + cc; gw = gw < 0 ? 0 : (gw > W-1 ? W-1 : gw);
        const float* src = in + ((size_t)(b*64 + chunk*8))*HW + gh*W + gw;
        unsigned short hb[8], lb[8];
        #pragma unroll
        for (int q = 0; q < 8; q++) {
            const int ci = chunk*8 + q;
            float2 mr = *(const float2*)(smem + OF_NRM + ci*8);
            float x = __ldg(src + (size_t)q*HW);
            x = (x - mr.x) * mr.y;
            x = x >= 0.f ? x : SLOPE * x;
            __half h = __float2half_rn(x);
            float xhf = __half2float(h);
            __half l = __float2half_rn((x - xhf) + CSPL*xhf);   // a2 = xl + c*xh
            hb[q] = *(unsigned short*)&h;
            lb[q] = *(unsigned short*)&l;
        }
        const uint32_t off = (uint32_t)r*128 + (uint32_t)((chunk ^ (r & 7)) << 4);
        *(uint4*)(smem + OF_WHI + off) = *(uint4*)hb;
        *(uint4*)(smem + OF_WLO + off) = *(uint4*)lb;
    }
    __syncthreads();

    // warp geometry: 4 M-strips (32 px = one image row) x 2 N-halves (32 co)
    const int mwid = wid >> 1;           // 0..3  (h row within tile)
    const int nwid = wid & 1;            // 0..1  (co half)
    const int gA  = lane >> 3;
    const int rl  = (lane & 7) + (gA & 1)*8;
    const int aK  = gA >> 1;

    float d1[2][4][4], d2[2][4][4];
    #pragma unroll
    for (int m = 0; m < 2; m++)
        #pragma unroll
        for (int n = 0; n < 4; n++)
            #pragma unroll
            for (int j = 0; j < 4; j++) { d1[m][n][j] = 0.f; d2[m][n][j] = 0.f; }

    const uint4* bwarp = wp + (size_t)nwid*128 + lane;   // + t*1024 + ks*256 + g4*32

    #pragma unroll 1
    for (int t = 0; t < 9; t++) {
        const int kh = t / 3, kw = t - kh*3;
        const int wr0 = (mwid + kh)*34 + kw + rl;
        const uint32_t aH = sb + OF_WHI + (uint32_t)wr0*128;
        const uint32_t aL = sb + OF_WLO + (uint32_t)wr0*128;
        const int asw = wr0 & 7;
        const uint4* btap = bwarp + (size_t)t*1024;

        #pragma unroll
        for (int ks = 0; ks < 4; ks++) {
            uint4 bfr[4];
            #pragma unroll
            for (int g4 = 0; g4 < 4; g4++)
                bfr[g4] = __ldg(btap + ks*256 + g4*32);

            uint32_t ah0[4], ah1[4], a20[4], a21[4];
            const uint32_t ca = (uint32_t)(((2*ks + aK) ^ asw) << 4);
            ldsm4(ah0, aH + ca);
            ldsm4(ah1, aH + 16*128 + ca);
            ldsm4(a20, aL + ca);
            ldsm4(a21, aL + 16*128 + ca);

            #pragma unroll
            for (int g4 = 0; g4 < 4; g4++) {
                const uint32_t bh[2] = {bfr[g4].x, bfr[g4].y};
                const uint32_t b2[2] = {bfr[g4].z, bfr[g4].w};
                mma16816h(d1[0][g4], ah0, bh);
                mma16816h(d1[1][g4], ah1, bh);
                mma16816h(d2[0][g4], a20, b2);
                mma16816h(d2[1][g4], a21, b2);
            }
        }
    }

    // ---- epilogue: combine (1-c)*D1 + D2 -> smem (stride 132) -> store + stats ----
    __syncthreads();   // all window reads done; safe to overwrite
    float* epi = (float*)smem;
    #pragma unroll
    for (int m = 0; m < 2; m++)
        #pragma unroll
        for (int n = 0; n < 4; n++)
            #pragma unroll
            for (int j = 0; j < 4; j++) {
                int co = nwid*32 + n*8 + (lane & 3)*2 + (j & 1);
                int wloc = m*16 + (lane >> 2) + ((j >> 1) << 3);
                epi[co*132 + mwid*32 + wloc] = fmaf(1.0f - CSPL, d1[m][n][j], d2[m][n][j]);
            }
    __syncthreads();

    {
        const int h0 = tileH*4, w0 = tileW*32;
        #pragma unroll 1
        for (int k = 0; k < 8; k++) {
            const int co = wid*8 + k;
            const float bv = __ldg(bias + co);
            float* op = out + ((size_t)(b*64 + co))*HW + (size_t)h0*W + w0;
            float s = 0.f, q = 0.f;
            #pragma unroll
            for (int i = 0; i < 4; i++) {
                float v = epi[co*132 + i*32 + lane] + bv;
                op[(size_t)i*W + lane] = v;
                s += v; q += v*v;
            }
            #pragma unroll
            for (int off = 16; off; off >>= 1) {
                s += __shfl_down_sync(0xffffffffu, s, off);
                q += __shfl_down_sync(0xffffffffu, q, off);
            }
            if (lane == 0) {
                atomicAdd(&statacc[(b*64 + co)*2    ], s);
                atomicAdd(&statacc[(b*64 + co)*2 + 1], q);
            }
        }
    }
}

// ---------------- stats -> (mean, rstd) ----------------
__global__ void finalize_kernel(const float* __restrict__ acc, float* __restrict__ nrm) {
    int i = blockIdx.x * blockDim.x + threadIdx.x;
    if (i < BSZ*CH) {
        const float inv = 1.f / (float)HW;
        float m = acc[2*i] * inv;
        float v = acc[2*i + 1] * inv - m*m;
        nrm[2*i]     = m;
        nrm[2*i + 1] = rsqrtf(v + EPS);
    }
}

// ---------------- layer-0 scalar conv (cin=1, proven) ----------------
__global__ __launch_bounds__(256, 2)
void conv_kernel(const float* __restrict__ in,
                 const float* __restrict__ wgt,
                 const float* __restrict__ bias,
                 const float* __restrict__ innorm,
                 float* __restrict__ out,
                 float* __restrict__ statacc,
                 int cin)
{
    __shared__ float s_w[64*9*16];
    __shared__ float s_in[2][18*36];

    const int tid   = threadIdx.x;
    const int tileW = blockIdx.x & 7;
    const int tileH = blockIdx.x >> 3;
    const int co_base = blockIdx.y * 16;
    const int b = blockIdx.z;

    const int nw = cin * 9 * 16;
    for (int g = tid; g < nw; g += 256) {
        int co_l = g & 15;
        int ct   = g >> 4;
        int ci   = ct / 9;
        int t    = ct - ci*9;
        s_w[g] = wgt[((co_base + co_l)*cin + ci)*9 + t];
    }

    const int sp = tid & 63, cg = tid >> 6;
    const int ph = sp >> 3, pw = sp & 7;
    const int h0 = tileH*16 + ph*2;
    const int w0 = tileW*32 + pw*4;
    const int hbase = tileH*16 - 1, wbase = tileW*32 - 1;

    int srcO[3], dstO[3]; bool act[3];
    #pragma unroll
    for (int k = 0; k < 3; k++) {
        int g = tid + k*256;
        act[k] = (g < 612);
        int gg = act[k] ? g : 0;
        int r = gg / 34, c = gg - r * 34;
        int gh = hbase + r; gh = gh < 0 ? 0 : (gh > H-1 ? H-1 : gh);
        int gw = wbase + c; gw = gw < 0 ? 0 : (gw > W-1 ? W-1 : gw);
        srcO[k] = gh*W + gw;
        dstO[k] = r*36 + c;
    }

    const float* inb = in + (size_t)b * cin * HW;

    {
        float mean = 0.f, rstd = 1.f;
        if (innorm) { mean = innorm[(b*cin)*2]; rstd = innorm[(b*cin)*2+1]; }
        #pragma unroll
        for (int k = 0; k < 3; k++) if (act[k]) {
            float v = inb[srcO[k]];
            if (innorm) { v = (v - mean) * rstd; v = v >= 0.f ? v : SLOPE * v; }
            s_in[0][dstO[k]] = v;
        }
    }
    __syncthreads();

    u64 acc[2][2][4];
    #pragma unroll
    for (int p = 0; p < 2; p++)
        #pragma unroll
        for (int i = 0; i < 2; i++)
            #pragma unroll
            for (int j = 0; j < 4; j++) acc[p][i][j] = 0ull;

    for (int ci = 0; ci < cin; ci++) {
        const int buf = ci & 1;
        const int cn = (ci + 1 < cin) ? ci + 1 : cin - 1;

        float pre[3];
        float nmean = 0.f, nrstd = 1.f;
        {
            const float* pn = inb + (size_t)cn * HW;
            if (innorm) {
                nmean = innorm[(b*cin + cn)*2];
                nrstd = innorm[(b*cin + cn)*2 + 1];
            }
            #pragma unroll
            for (int k = 0; k < 3; k++) pre[k] = act[k] ? pn[srcO[k]] : 0.f;
        }

        u64 dup[4][6];
        #pragma unroll
        for (int r = 0; r < 4; r++) {
            const float* row = &s_in[buf][(ph*2 + r)*36 + pw*4];
            float4 v4 = *reinterpret_cast<const float4*>(row);
            float2 v2 = *reinterpret_cast<const float2*>(row + 4);
            PACK2(dup[r][0], v4.x, v4.x);
            PACK2(dup[r][1], v4.y, v4.y);
            PACK2(dup[r][2], v4.z, v4.z);
            PACK2(dup[r][3], v4.w, v4.w);
            PACK2(dup[r][4], v2.x, v2.x);
            PACK2(dup[r][5], v2.y, v2.y);
        }

        const float* wrow = &s_w[ci*9*16 + cg*4];
        #pragma unroll
        for (int p = 0; p < 2; p++) {
            u64 wv[9];
            #pragma unroll
            for (int t = 0; t < 9; t++)
                wv[t] = *reinterpret_cast<const u64*>(&wrow[t*16 + p*2]);
            #pragma unroll
            for (int kh = 0; kh < 3; kh++)
                #pragma unroll
                for (int kw = 0; kw < 3; kw++)
                    #pragma unroll
                    for (int i = 0; i < 2; i++)
                        #pragma unroll
                        for (int j = 0; j < 4; j++)
                            FMA2(acc[p][i][j], dup[i+kh][j+kw], wv[kh*3+kw], acc[p][i][j]);
        }

        #pragma unroll
        for (int k = 0; k < 3; k++) if (act[k]) {
            float v = pre[k];
            if (innorm) { v = (v - nmean) * nrstd; v = v >= 0.f ? v : SLOPE * v; }
            s_in[buf ^ 1][dstO[k]] = v;
        }
        __syncthreads();
    }

    #pragma unroll
    for (int p = 0; p < 2; p++) {
        const int co0 = co_base + cg*4 + 2*p;
        const float bv0 = bias[co0], bv1 = bias[co0 + 1];
        float* ob0 = out + (size_t)(b*CH + co0    ) * HW;
        float* ob1 = out + (size_t)(b*CH + co0 + 1) * HW;
        float s0 = 0.f, q0 = 0.f, s1 = 0.f, q1 = 0.f;
        #pragma unroll
        for (int i = 0; i < 2; i++) {
            float lo[4], hi[4];
            #pragma unroll
            for (int j = 0; j < 4; j++) {
                float l, h2;
                UNPK2(l, h2, acc[p][i][j]);
                lo[j] = l + bv0; hi[j] = h2 + bv1;
                s0 += lo[j]; q0 += lo[j]*lo[j];
                s1 += hi[j]; q1 += hi[j]*hi[j];
            }
            *reinterpret_cast<float4*>(&ob0[(h0+i)*W + w0]) = make_float4(lo[0],lo[1],lo[2],lo[3]);
            *reinterpret_cast<float4*>(&ob1[(h0+i)*W + w0]) = make_float4(hi[0],hi[1],hi[2],hi[3]);
        }
        #pragma unroll
        for (int off = 16; off; off >>= 1) {
            s0 += __shfl_down_sync(0xffffffffu, s0, off);
            q0 += __shfl_down_sync(0xffffffffu, q0, off);
            s1 += __shfl_down_sync(0xffffffffu, s1, off);
            q1 += __shfl_down_sync(0xffffffffu, q1, off);
        }
        if ((tid & 31) == 0) {
            atomicAdd(&statacc[(b*CH + co0)*2    ], s0);
            atomicAdd(&statacc[(b*CH + co0)*2 + 1], q0);
            atomicAdd(&statacc[(b*CH + co0+1)*2    ], s1);
            atomicAdd(&statacc[(b*CH + co0+1)*2 + 1], q1);
        }
    }
}

// ---------------- projection conv (64->1) + residual: 16x32 tile, dbl-buffered ----------------
__global__ __launch_bounds__(256)
void proj_kernel(const float* __restrict__ in, const float* __restrict__ innorm,
                 const float* __restrict__ wgt, const float* __restrict__ bias,
                 const float* __restrict__ xIn, float* __restrict__ out)
{
    __shared__ float s_w[64*9];
    __shared__ float s_in[2][18*36];
    const int tid = threadIdx.x;
    const int tileW = blockIdx.x & 7;
    const int tileH = blockIdx.x >> 3;   // 0..15
    const int b = blockIdx.z;

    for (int g = tid; g < 576; g += 256) s_w[g] = wgt[g];

    const int pw = tid & 31, hp = tid >> 5;  // w 0..31, hpair 0..7
    const int h0 = tileH*16 + hp*2;
    const int w0 = tileW*32 + pw;
    const int hbase = tileH*16 - 1, wbase = tileW*32 - 1;

    int srcO[3], dstO[3]; bool act[3];
    #pragma unroll
    for (int k = 0; k < 3; k++) {
        int g = tid + k*256;
        act[k] = (g < 612);
        int gg = act[k] ? g : 0;
        int r = gg / 34, c = gg - r*34;
        int gh = hbase + r; gh = gh < 0 ? 0 : (gh > H-1 ? H-1 : gh);
        int gw = wbase + c; gw = gw < 0 ? 0 : (gw > W-1 ? W-1 : gw);
        srcO[k] = gh*W + gw;
        dstO[k] = r*36 + c;
    }

    const float* inb = in + (size_t)b*64*HW;
    const float2* nrmb = (const float2*)innorm + b*64;

    {
        float2 mr = nrmb[0];
        #pragma unroll
        for (int k = 0; k < 3; k++) if (act[k]) {
            float v = inb[srcO[k]];
            v = (v - mr.x) * mr.y;
            v = v >= 0.f ? v : SLOPE * v;
            s_in[0][dstO[k]] = v;
        }
    }
    __syncthreads();

    float acc0 = 0.f, acc1 = 0.f;
    for (int ci = 0; ci < 64; ci++) {
        const int buf = ci & 1;
        const int cn = (ci + 1 < 64) ? ci + 1 : 63;
        float pre[3];
        float2 nmr = nrmb[cn];
        {
            const float* pn = inb + (size_t)cn*HW;
            #pragma unroll
            for (int k = 0; k < 3; k++) pre[k] = act[k] ? pn[srcO[k]] : 0.f;
        }

        float rr[4][3];
        #pragma unroll
        for (int r = 0; r < 4; r++)
            #pragma unroll
            for (int c = 0; c < 3; c++)
                rr[r][c] = s_in[buf][(hp*2 + r)*36 + pw + c];

        const float* wv = &s_w[ci*9];
        #pragma unroll
        for (int kh = 0; kh < 3; kh++)
            #pragma unroll
            for (int kw = 0; kw < 3; kw++) {
                float wvv = wv[kh*3 + kw];
                acc0 = fmaf(rr[kh    ][kw], wvv, acc0);
                acc1 = fmaf(rr[kh + 1][kw], wvv, acc1);
            }

        #pragma unroll
        for (int k = 0; k < 3; k++) if (act[k]) {
            float v = pre[k];
            v = (v - nmr.x) * nmr.y;
            v = v >= 0.f ? v : SLOPE * v;
            s_in[buf ^ 1][dstO[k]] = v;
        }
        __syncthreads();
    }

    int idx = b*HW + h0*W + w0;
    out[idx]     = acc0 + bias[0] + xIn[idx];
    out[idx + W] = acc1 + bias[0] + xIn[idx + W];
}

// ---------------- shift-search loss ----------------
__global__ __launch_bounds__(256)
void loss_kernel(const float* __restrict__ hr, const float* __restrict__ tgt,
                 float* __restrict__ loss_sb)
{
    const int s = blockIdx.x, b = blockIdx.y;
    const int sy = s / 13, sx = s - sy*13;
    const float* hp = hr + (size_t)b * HW;
    const float* tp = tgt + (size_t)b * HW;
    const int tid = threadIdx.x;

    float sum = 0.f, sq = 0.f;
    if (tid < CROP) {
        for (int r = 0; r < CROP; r++) {
            float d = hp[(sy + r)*W + sx + tid] - tp[(6 + r)*W + 6 + tid];
            sum += d; sq += d*d;
        }
    }
    __shared__ float s1[256], s2[256];
    s1[tid] = sum; s2[tid] = sq;
    __syncthreads();
    for (int off = 128; off; off >>= 1) {
        if (tid < off) { s1[tid] += s1[tid + off]; s2[tid] += s2[tid + off]; }
        __syncthreads();
    }
    if (tid == 0) {
        const float invN = 1.f / (float)(CROP*CROP);
        float m = s1[0] * invN;
        loss_sb[s*BSZ + b] = s2[0] * invN - m*m;
    }
}

__global__ void loss_final_kernel(const float* __restrict__ loss_sb, float* __restrict__ out) {
    __shared__ float mn[BSZ];
    int t = threadIdx.x;
    if (t < BSZ) {
        float m = loss_sb[t];
        for (int s = 1; s < 169; s++) m = fminf(m, loss_sb[s*BSZ + t]);
        mn[t] = m;
    }
    __syncthreads();
    if (t == 0) {
        float a = 0.f;
        for (int b = 0; b < BSZ; b++) a += mn[b];
        out[0] = a * (1.f / BSZ);
    }
}

// ---------------- launch ----------------
extern "C" void kernel_launch(void* const* d_in, const int* in_sizes, int n_in,
                              void* d_out, int out_size)
{
    const float* xIn    = (const float*)d_in[0];
    const float* target = (const float*)d_in[1];
    const float* w0     = (const float*)d_in[2];
    const float* b0     = (const float*)d_in[3];
    const float* ws     = (const float*)d_in[4];
    const float* bs     = (const float*)d_in[5];
    const float* wp     = (const float*)d_in[6];
    const float* bp     = (const float*)d_in[7];
    float* out = (float*)d_out;

    static int attr_done = 0;
    if (!attr_done) {
        cudaFuncSetAttribute(mma_conv_kernel, cudaFuncAttributeMaxDynamicSharedMemorySize, SMEM_MMA);
        attr_done = 1;
    }

    float *actA, *actB, *stats, *nrm, *lsb;
    uint4* wprep;
    cudaGetSymbolAddress((void**)&actA,  g_actA);
    cudaGetSymbolAddress((void**)&actB,  g_actB);
    cudaGetSymbolAddress((void**)&stats, g_stats);
    cudaGetSymbolAddress((void**)&nrm,   g_norm);
    cudaGetSymbolAddress((void**)&lsb,   g_loss_sb);
    cudaGetSymbolAddress((void**)&wprep, g_wprep);

    wprep_kernel<<<dim3(9, 7), 256>>>(ws);
    zero_stats_kernel<<<1, 256>>>();

    // layer 0 (1 -> 64): scalar path, stats slot 0
    conv_kernel<<<dim3(128, 4, BSZ), 256>>>(xIn, w0, b0, nullptr, actA, stats, 1);
    finalize_kernel<<<2, 256>>>(stats, nrm);

    const float* cur = actA;
    float* nxt = actB;
    for (int i = 0; i < 7; i++) {
        mma_conv_kernel<<<dim3(8, 64, BSZ), 256, SMEM_MMA>>>(
            cur, wprep + (size_t)i*9*1024, bs + i*64,
            nrm + (size_t)i*BSZ*CH*2, nxt, stats + (size_t)(i+1)*BSZ*CH*2);
        finalize_kernel<<<2, 256>>>(stats + (size_t)(i+1)*BSZ*CH*2,
                                    nrm   + (size_t)(i+1)*BSZ*CH*2);
        float* tmp = (float*)cur; cur = nxt; nxt = tmp;
    }

    proj_kernel<<<dim3(128, 1, BSZ), 256>>>(cur, nrm + (size_t)7*BSZ*CH*2,
                                            wp, bp, xIn, out);
    loss_kernel<<<dim3(169, BSZ), 256>>>(out, target, lsb);
    loss_final_kernel<<<1, 32>>>(lsb, out + (out_size - 1));
}

// round 11
// speedup vs baseline: 1.7861x; 1.7861x over previous
#include <cuda_runtime.h>
#include <cuda_fp16.h>
#include <cstdint>

#define BSZ 8
#define CH  64
#define H   256
#define W   256
#define HW  (H*W)
#define EPS 1e-5f
#define SLOPE 0.01f
#define CROP 244
#define CSPL 0.03125f   // c = 2^-5 split-compensation constant

typedef unsigned long long u64;

#define FMA2(d,a,b,c) asm("fma.rn.f32x2 %0, %1, %2, %3;" : "=l"(d) : "l"(a), "l"(b), "l"(c))
#define PACK2(d,lo,hi) asm("mov.b64 %0, {%1, %2};" : "=l"(d) : "f"(lo), "f"(hi))
#define UNPK2(lo,hi,d) asm("mov.b64 {%0, %1}, %2;" : "=f"(lo), "=f"(hi) : "l"(d))

__device__ __forceinline__ uint32_t smem_u32(const void* p) {
    uint32_t a;
    asm("{ .reg .u64 t; cvta.to.shared.u64 t, %1; cvt.u32.u64 %0, t; }" : "=r"(a) : "l"(p));
    return a;
}
__device__ __forceinline__ void ldsm4(uint32_t* r, uint32_t addr) {
    asm volatile("ldmatrix.sync.aligned.m8n8.x4.shared.b16 {%0,%1,%2,%3}, [%4];"
                 : "=r"(r[0]), "=r"(r[1]), "=r"(r[2]), "=r"(r[3]) : "r"(addr));
}
__device__ __forceinline__ void mma16816h(float* d, const uint32_t* a, const uint32_t* b) {
    asm volatile("mma.sync.aligned.m16n8k16.row.col.f32.f16.f16.f32 "
                 "{%0,%1,%2,%3}, {%4,%5,%6,%7}, {%8,%9}, {%0,%1,%2,%3};"
                 : "+f"(d[0]), "+f"(d[1]), "+f"(d[2]), "+f"(d[3])
                 : "r"(a[0]), "r"(a[1]), "r"(a[2]), "r"(a[3]), "r"(b[0]), "r"(b[1]));
}

// ---------------- scratch ----------------
__device__ float g_actA[BSZ*CH*HW];
__device__ float g_actB[BSZ*CH*HW];
__device__ float g_stats[8*BSZ*CH*2];
__device__ float g_norm[8*BSZ*CH*2];
__device__ float g_loss_sb[169*BSZ];
// [layer][img(bh=0,b2=1)][tap][4096] fp16 ldmatrix-swizzled co x ci images
__device__ __half g_wprep[7*2*9*4096];

__global__ void zero_stats_kernel() {
    for (int i = threadIdx.x; i < 8*BSZ*CH*2; i += blockDim.x) g_stats[i] = 0.f;
}

// ---------------- weight prep: wh image + compensated w2 image ----------------
// image layout: byte_off = co*128 + (((ci>>3) ^ (co&7))<<4) + (ci&7)*2
__global__ void wprep_kernel(const float* __restrict__ ws) {
    const int t = blockIdx.x;    // tap 0..8
    const int l = blockIdx.y;    // layer 0..6
    char* dst0 = (char*)(g_wprep + ((size_t)l*18 +     t)*4096);   // bh
    char* dst1 = (char*)(g_wprep + ((size_t)l*18 + 9 + t)*4096);   // b2
    for (int g = threadIdx.x; g < 4096; g += blockDim.x) {
        int co = g >> 6, ci = g & 63;
        float w = ws[(((size_t)l*64 + co)*64 + ci)*9 + t];
        __half wh = __float2half_rn(w);
        float whf = __half2float(wh);
        __half w2 = __float2half_rn(whf + 32.0f*(w - whf));   // wh + wl/c
        uint32_t off = (uint32_t)co*128 + ((((uint32_t)ci >> 3) ^ (co & 7)) << 4) + (ci & 7)*2;
        *(__half*)(dst0 + off) = wh;
        *(__half*)(dst1 + off) = w2;
    }
}

// ---------------- HMMA conv layer: M256 tile, sequential compensated 2-pass ----------------
// smem: window xh [340*128B], window a2 [340*128B], B dbl [2*8KB], nrm [512B]
#define OF_WHI 0
#define OF_WLO 43520
#define OF_B   87040
#define OF_NRM 103424
#define SMEM_MMA 103936
#define EPI_STRIDE 264

__global__ void __launch_bounds__(256, 2)
mma_conv_kernel(const float* __restrict__ in,
                const __half* __restrict__ wp,          // this layer: [2][9][4096]
                const float* __restrict__ bias,
                const float* __restrict__ nrm,          // [BSZ*64*2] (mean,rstd)
                float* __restrict__ out,
                float* __restrict__ statacc)            // [BSZ*64*2]
{
    extern __shared__ char smem[];
    const uint32_t sb = smem_u32(smem);
    const int tid = threadIdx.x;
    const int wid = tid >> 5, lane = tid & 31;
    const int tileW = blockIdx.x;   // 0..7   (32 w)
    const int tileH = blockIdx.y;   // 0..31  (8 h)
    const int b = blockIdx.z;

    if (tid < 64)
        *(float2*)(smem + OF_NRM + tid*8) = ((const float2*)nrm)[b*64 + tid];
    __syncthreads();   // nrm visible before window fill

    // ---- window fill: 340 rows (10h x 34w) x 64 ci ----
    for (int g = tid; g < 2720; g += 256) {
        const int chunk = g / 340;
        const int r = g - chunk*340;
        const int rr = r / 34, cc = r - rr*34;
        int gh = tileH*8 - 1 + rr; gh = gh < 0 ? 0 : (gh > H-1 ? H-1 : gh);
        int gw = tileW*32 - 1 + cc; gw = gw < 0 ? 0 : (gw > W-1 ? W-1 : gw);
        const float* src = in + ((size_t)(b*64 + chunk*8))*HW + gh*W + gw;
        unsigned short hb[8], lb[8];
        #pragma unroll
        for (int q = 0; q < 8; q++) {
            const int ci = chunk*8 + q;
            float2 mr = *(const float2*)(smem + OF_NRM + ci*8);
            float x = __ldg(src + (size_t)q*HW);
            x = (x - mr.x) * mr.y;
            x = x >= 0.f ? x : SLOPE * x;
            __half h = __float2half_rn(x);
            float xhf = __half2float(h);
            __half l = __float2half_rn((x - xhf) + CSPL*xhf);   // a2 = xl + c*xh
            hb[q] = *(unsigned short*)&h;
            lb[q] = *(unsigned short*)&l;
        }
        const uint32_t off = (uint32_t)r*128 + (uint32_t)((chunk ^ (r & 7)) << 4);
        *(uint4*)(smem + OF_WHI + off) = *(uint4*)hb;
        *(uint4*)(smem + OF_WLO + off) = *(uint4*)lb;
    }

    // ---- stage B for tt=0 (bh, tap 0) into buffer 0 ----
    const uint4* wp4 = (const uint4*)wp;   // [18][512] uint4
    *(uint4*)(smem + OF_B + (uint32_t)tid*16)         = __ldg(wp4 + tid);
    *(uint4*)(smem + OF_B + (uint32_t)(tid + 256)*16) = __ldg(wp4 + tid + 256);
    __syncthreads();

    // warp geometry: 4 M-strips (64 px = two h-rows) x 2 N-halves (32 co)
    const int mwid = wid >> 1;           // 0..3
    const int nwid = wid & 1;            // 0..1
    const int gA  = lane >> 3;
    const int rl  = (lane & 7) + (gA & 1)*8;
    const int aK  = gA >> 1;
    const int bRow = (lane & 7) + ((lane >> 4) & 1)*8;
    const int bK   = (lane >> 3) & 1;
    const int bsw  = lane & 7;

    float d[4][4][4];   // [mf][n8][frag]
    #pragma unroll
    for (int mf = 0; mf < 4; mf++)
        #pragma unroll
        for (int n = 0; n < 4; n++)
            #pragma unroll
            for (int j = 0; j < 4; j++) d[mf][n][j] = 0.f;

    #pragma unroll 1
    for (int tt = 0; tt < 18; tt++) {
        // prefetch next stage's B image tap
        uint4 pre0, pre1;
        if (tt < 17) {
            const uint4* np = wp4 + (size_t)(tt + 1)*512;
            pre0 = __ldg(np + tid);
            pre1 = __ldg(np + tid + 256);
        }

        // between passes: d *= (1 - c)  (exactly once, after all pass-1 MMAs)
        if (tt == 9) {
            #pragma unroll
            for (int mf = 0; mf < 4; mf++)
                #pragma unroll
                for (int n = 0; n < 4; n++)
                    #pragma unroll
                    for (int j = 0; j < 4; j++) d[mf][n][j] *= (1.0f - CSPL);
        }

        const int t  = tt < 9 ? tt : tt - 9;
        const int kh = t / 3, kw = t - kh*3;
        const uint32_t aBase = sb + (tt < 9 ? OF_WHI : OF_WLO);
        int wr[4];
        #pragma unroll
        for (int mf = 0; mf < 4; mf++) {
            const int hh = mwid*2 + (mf >> 1);
            wr[mf] = (hh + kh)*34 + (mf & 1)*16 + kw + rl;
        }
        const uint32_t bB = sb + OF_B + (uint32_t)(tt & 1)*8192;

        #pragma unroll
        for (int ks = 0; ks < 4; ks++) {
            uint32_t a[4][4];
            #pragma unroll
            for (int mf = 0; mf < 4; mf++)
                ldsm4(a[mf], aBase + (uint32_t)wr[mf]*128
                              + (uint32_t)(((2*ks + aK) ^ (wr[mf] & 7)) << 4));
            uint32_t bf[2][4];
            const uint32_t cb = (uint32_t)(((2*ks + bK) ^ bsw) << 4);
            #pragma unroll
            for (int nn = 0; nn < 2; nn++)
                ldsm4(bf[nn], bB + (uint32_t)((nwid*2 + nn)*16 + bRow)*128 + cb);
            #pragma unroll
            for (int mf = 0; mf < 4; mf++)
                #pragma unroll
                for (int n = 0; n < 4; n++)
                    mma16816h(d[mf][n], a[mf], &bf[n >> 1][(n & 1)*2]);
        }

        if (tt < 17) {
            char* dst = smem + OF_B + (uint32_t)((tt + 1) & 1)*8192;
            *(uint4*)(dst + (uint32_t)tid*16)         = pre0;
            *(uint4*)(dst + (uint32_t)(tid + 256)*16) = pre1;
            __syncthreads();
        }
    }

    // ---- epilogue: d -> smem (stride 264) -> coalesced store + fused stats ----
    __syncthreads();   // window reads done; safe to overwrite
    float* epi = (float*)smem;
    #pragma unroll
    for (int mf = 0; mf < 4; mf++)
        #pragma unroll
        for (int n = 0; n < 4; n++)
            #pragma unroll
            for (int j = 0; j < 4; j++) {
                const int r16 = (lane >> 2) + ((j >> 1) << 3);
                const int px = (mwid*2 + (mf >> 1))*32 + (mf & 1)*16 + r16;
                const int co = nwid*32 + n*8 + (lane & 3)*2 + (j & 1);
                epi[co*EPI_STRIDE + px] = d[mf][n][j];
            }
    __syncthreads();

    {
        const int h0 = tileH*8, w0 = tileW*32;
        #pragma unroll 1
        for (int k = 0; k < 8; k++) {
            const int co = wid*8 + k;
            const float bv = __ldg(bias + co);
            float* op = out + ((size_t)(b*64 + co))*HW + (size_t)h0*W + w0;
            float s = 0.f, q = 0.f;
            #pragma unroll
            for (int i = 0; i < 8; i++) {
                float v = epi[co*EPI_STRIDE + i*32 + lane] + bv;
                op[(size_t)i*W + lane] = v;
                s += v; q += v*v;
            }
            #pragma unroll
            for (int off = 16; off; off >>= 1) {
                s += __shfl_down_sync(0xffffffffu, s, off);
                q += __shfl_down_sync(0xffffffffu, q, off);
            }
            if (lane == 0) {
                atomicAdd(&statacc[(b*64 + co)*2    ], s);
                atomicAdd(&statacc[(b*64 + co)*2 + 1], q);
            }
        }
    }
}

// ---------------- stats -> (mean, rstd) ----------------
__global__ void finalize_kernel(const float* __restrict__ acc, float* __restrict__ nrm) {
    int i = blockIdx.x * blockDim.x + threadIdx.x;
    if (i < BSZ*CH) {
        const float inv = 1.f / (float)HW;
        float m = acc[2*i] * inv;
        float v = acc[2*i + 1] * inv - m*m;
        nrm[2*i]     = m;
        nrm[2*i + 1] = rsqrtf(v + EPS);
    }
}

// ---------------- layer-0 scalar conv (cin=1, proven) ----------------
__global__ __launch_bounds__(256, 2)
void conv_kernel(const float* __restrict__ in,
                 const float* __restrict__ wgt,
                 const float* __restrict__ bias,
                 const float* __restrict__ innorm,
                 float* __restrict__ out,
                 float* __restrict__ statacc,
                 int cin)
{
    __shared__ float s_w[64*9*16];
    __shared__ float s_in[2][18*36];

    const int tid   = threadIdx.x;
    const int tileW = blockIdx.x & 7;
    const int tileH = blockIdx.x >> 3;
    const int co_base = blockIdx.y * 16;
    const int b = blockIdx.z;

    const int nw = cin * 9 * 16;
    for (int g = tid; g < nw; g += 256) {
        int co_l = g & 15;
        int ct   = g >> 4;
        int ci   = ct / 9;
        int t    = ct - ci*9;
        s_w[g] = wgt[((co_base + co_l)*cin + ci)*9 + t];
    }

    const int sp = tid & 63, cg = tid >> 6;
    const int ph = sp >> 3, pw = sp & 7;
    const int h0 = tileH*16 + ph*2;
    const int w0 = tileW*32 + pw*4;
    const int hbase = tileH*16 - 1, wbase = tileW*32 - 1;

    int srcO[3], dstO[3]; bool act[3];
    #pragma unroll
    for (int k = 0; k < 3; k++) {
        int g = tid + k*256;
        act[k] = (g < 612);
        int gg = act[k] ? g : 0;
        int r = gg / 34, c = gg - r * 34;
        int gh = hbase + r; gh = gh < 0 ? 0 : (gh > H-1 ? H-1 : gh);
        int gw = wbase + c; gw = gw < 0 ? 0 : (gw > W-1 ? W-1 : gw);
        srcO[k] = gh*W + gw;
        dstO[k] = r*36 + c;
    }

    const float* inb = in + (size_t)b * cin * HW;

    {
        float mean = 0.f, rstd = 1.f;
        if (innorm) { mean = innorm[(b*cin)*2]; rstd = innorm[(b*cin)*2+1]; }
        #pragma unroll
        for (int k = 0; k < 3; k++) if (act[k]) {
            float v = inb[srcO[k]];
            if (innorm) { v = (v - mean) * rstd; v = v >= 0.f ? v : SLOPE * v; }
            s_in[0][dstO[k]] = v;
        }
    }
    __syncthreads();

    u64 acc[2][2][4];
    #pragma unroll
    for (int p = 0; p < 2; p++)
        #pragma unroll
        for (int i = 0; i < 2; i++)
            #pragma unroll
            for (int j = 0; j < 4; j++) acc[p][i][j] = 0ull;

    for (int ci = 0; ci < cin; ci++) {
        const int buf = ci & 1;
        const int cn = (ci + 1 < cin) ? ci + 1 : cin - 1;

        float pre[3];
        float nmean = 0.f, nrstd = 1.f;
        {
            const float* pn = inb + (size_t)cn * HW;
            if (innorm) {
                nmean = innorm[(b*cin + cn)*2];
                nrstd = innorm[(b*cin + cn)*2 + 1];
            }
            #pragma unroll
            for (int k = 0; k < 3; k++) pre[k] = act[k] ? pn[srcO[k]] : 0.f;
        }

        u64 dup[4][6];
        #pragma unroll
        for (int r = 0; r < 4; r++) {
            const float* row = &s_in[buf][(ph*2 + r)*36 + pw*4];
            float4 v4 = *reinterpret_cast<const float4*>(row);
            float2 v2 = *reinterpret_cast<const float2*>(row + 4);
            PACK2(dup[r][0], v4.x, v4.x);
            PACK2(dup[r][1], v4.y, v4.y);
            PACK2(dup[r][2], v4.z, v4.z);
            PACK2(dup[r][3], v4.w, v4.w);
            PACK2(dup[r][4], v2.x, v2.x);
            PACK2(dup[r][5], v2.y, v2.y);
        }

        const float* wrow = &s_w[ci*9*16 + cg*4];
        #pragma unroll
        for (int p = 0; p < 2; p++) {
            u64 wv[9];
            #pragma unroll
            for (int t = 0; t < 9; t++)
                wv[t] = *reinterpret_cast<const u64*>(&wrow[t*16 + p*2]);
            #pragma unroll
            for (int kh = 0; kh < 3; kh++)
                #pragma unroll
                for (int kw = 0; kw < 3; kw++)
                    #pragma unroll
                    for (int i = 0; i < 2; i++)
                        #pragma unroll
                        for (int j = 0; j < 4; j++)
                            FMA2(acc[p][i][j], dup[i+kh][j+kw], wv[kh*3+kw], acc[p][i][j]);
        }

        #pragma unroll
        for (int k = 0; k < 3; k++) if (act[k]) {
            float v = pre[k];
            if (innorm) { v = (v - nmean) * nrstd; v = v >= 0.f ? v : SLOPE * v; }
            s_in[buf ^ 1][dstO[k]] = v;
        }
        __syncthreads();
    }

    #pragma unroll
    for (int p = 0; p < 2; p++) {
        const int co0 = co_base + cg*4 + 2*p;
        const float bv0 = bias[co0], bv1 = bias[co0 + 1];
        float* ob0 = out + (size_t)(b*CH + co0    ) * HW;
        float* ob1 = out + (size_t)(b*CH + co0 + 1) * HW;
        float s0 = 0.f, q0 = 0.f, s1 = 0.f, q1 = 0.f;
        #pragma unroll
        for (int i = 0; i < 2; i++) {
            float lo[4], hi[4];
            #pragma unroll
            for (int j = 0; j < 4; j++) {
                float l, h2;
                UNPK2(l, h2, acc[p][i][j]);
                lo[j] = l + bv0; hi[j] = h2 + bv1;
                s0 += lo[j]; q0 += lo[j]*lo[j];
                s1 += hi[j]; q1 += hi[j]*hi[j];
            }
            *reinterpret_cast<float4*>(&ob0[(h0+i)*W + w0]) = make_float4(lo[0],lo[1],lo[2],lo[3]);
            *reinterpret_cast<float4*>(&ob1[(h0+i)*W + w0]) = make_float4(hi[0],hi[1],hi[2],hi[3]);
        }
        #pragma unroll
        for (int off = 16; off; off >>= 1) {
            s0 += __shfl_down_sync(0xffffffffu, s0, off);
            q0 += __shfl_down_sync(0xffffffffu, q0, off);
            s1 += __shfl_down_sync(0xffffffffu, s1, off);
            q1 += __shfl_down_sync(0xffffffffu, q1, off);
        }
        if ((tid & 31) == 0) {
            atomicAdd(&statacc[(b*CH + co0)*2    ], s0);
            atomicAdd(&statacc[(b*CH + co0)*2 + 1], q0);
            atomicAdd(&statacc[(b*CH + co0+1)*2    ], s1);
            atomicAdd(&statacc[(b*CH + co0+1)*2 + 1], q1);
        }
    }
}

// ---------------- projection conv (64->1) + residual: 16x32 tile, dbl-buffered ----------------
__global__ __launch_bounds__(256)
void proj_kernel(const float* __restrict__ in, const float* __restrict__ innorm,
                 const float* __restrict__ wgt, const float* __restrict__ bias,
                 const float* __restrict__ xIn, float* __restrict__ out)
{
    __shared__ float s_w[64*9];
    __shared__ float s_in[2][18*36];
    const int tid = threadIdx.x;
    const int tileW = blockIdx.x & 7;
    const int tileH = blockIdx.x >> 3;   // 0..15
    const int b = blockIdx.z;

    for (int g = tid; g < 576; g += 256) s_w[g] = wgt[g];

    const int pw = tid & 31, hp = tid >> 5;  // w 0..31, hpair 0..7
    const int h0 = tileH*16 + hp*2;
    const int w0 = tileW*32 + pw;
    const int hbase = tileH*16 - 1, wbase = tileW*32 - 1;

    int srcO[3], dstO[3]; bool act[3];
    #pragma unroll
    for (int k = 0; k < 3; k++) {
        int g = tid + k*256;
        act[k] = (g < 612);
        int gg = act[k] ? g : 0;
        int r = gg / 34, c = gg - r*34;
        int gh = hbase + r; gh = gh < 0 ? 0 : (gh > H-1 ? H-1 : gh);
        int gw = wbase + c; gw = gw < 0 ? 0 : (gw > W-1 ? W-1 : gw);
        srcO[k] = gh*W + gw;
        dstO[k] = r*36 + c;
    }

    const float* inb = in + (size_t)b*64*HW;
    const float2* nrmb = (const float2*)innorm + b*64;

    {
        float2 mr = nrmb[0];
        #pragma unroll
        for (int k = 0; k < 3; k++) if (act[k]) {
            float v = inb[srcO[k]];
            v = (v - mr.x) * mr.y;
            v = v >= 0.f ? v : SLOPE * v;
            s_in[0][dstO[k]] = v;
        }
    }
    __syncthreads();

    float acc0 = 0.f, acc1 = 0.f;
    for (int ci = 0; ci < 64; ci++) {
        const int buf = ci & 1;
        const int cn = (ci + 1 < 64) ? ci + 1 : 63;
        float pre[3];
        float2 nmr = nrmb[cn];
        {
            const float* pn = inb + (size_t)cn*HW;
            #pragma unroll
            for (int k = 0; k < 3; k++) pre[k] = act[k] ? pn[srcO[k]] : 0.f;
        }

        float rr[4][3];
        #pragma unroll
        for (int r = 0; r < 4; r++)
            #pragma unroll
            for (int c = 0; c < 3; c++)
                rr[r][c] = s_in[buf][(hp*2 + r)*36 + pw + c];

        const float* wv = &s_w[ci*9];
        #pragma unroll
        for (int kh = 0; kh < 3; kh++)
            #pragma unroll
            for (int kw = 0; kw < 3; kw++) {
                float wvv = wv[kh*3 + kw];
                acc0 = fmaf(rr[kh    ][kw], wvv, acc0);
                acc1 = fmaf(rr[kh + 1][kw], wvv, acc1);
            }

        #pragma unroll
        for (int k = 0; k < 3; k++) if (act[k]) {
            float v = pre[k];
            v = (v - nmr.x) * nmr.y;
            v = v >= 0.f ? v : SLOPE * v;
            s_in[buf ^ 1][dstO[k]] = v;
        }
        __syncthreads();
    }

    int idx = b*HW + h0*W + w0;
    out[idx]     = acc0 + bias[0] + xIn[idx];
    out[idx + W] = acc1 + bias[0] + xIn[idx + W];
}

// ---------------- shift-search loss ----------------
__global__ __launch_bounds__(256)
void loss_kernel(const float* __restrict__ hr, const float* __restrict__ tgt,
                 float* __restrict__ loss_sb)
{
    const int s = blockIdx.x, b = blockIdx.y;
    const int sy = s / 13, sx = s - sy*13;
    const float* hp = hr + (size_t)b * HW;
    const float* tp = tgt + (size_t)b * HW;
    const int tid = threadIdx.x;

    float sum = 0.f, sq = 0.f;
    if (tid < CROP) {
        for (int r = 0; r < CROP; r++) {
            float d = hp[(sy + r)*W + sx + tid] - tp[(6 + r)*W + 6 + tid];
            sum += d; sq += d*d;
        }
    }
    __shared__ float s1[256], s2[256];
    s1[tid] = sum; s2[tid] = sq;
    __syncthreads();
    for (int off = 128; off; off >>= 1) {
        if (tid < off) { s1[tid] += s1[tid + off]; s2[tid] += s2[tid + off]; }
        __syncthreads();
    }
    if (tid == 0) {
        const float invN = 1.f / (float)(CROP*CROP);
        float m = s1[0] * invN;
        loss_sb[s*BSZ + b] = s2[0] * invN - m*m;
    }
}

__global__ void loss_final_kernel(const float* __restrict__ loss_sb, float* __restrict__ out) {
    __shared__ float mn[BSZ];
    int t = threadIdx.x;
    if (t < BSZ) {
        float m = loss_sb[t];
        for (int s = 1; s < 169; s++) m = fminf(m, loss_sb[s*BSZ + t]);
        mn[t] = m;
    }
    __syncthreads();
    if (t == 0) {
        float a = 0.f;
        for (int b = 0; b < BSZ; b++) a += mn[b];
        out[0] = a * (1.f / BSZ);
    }
}

// ---------------- launch ----------------
extern "C" void kernel_launch(void* const* d_in, const int* in_sizes, int n_in,
                              void* d_out, int out_size)
{
    const float* xIn    = (const float*)d_in[0];
    const float* target = (const float*)d_in[1];
    const float* w0     = (const float*)d_in[2];
    const float* b0     = (const float*)d_in[3];
    const float* ws     = (const float*)d_in[4];
    const float* bs     = (const float*)d_in[5];
    const float* wp     = (const float*)d_in[6];
    const float* bp     = (const float*)d_in[7];
    float* out = (float*)d_out;

    static int attr_done = 0;
    if (!attr_done) {
        cudaFuncSetAttribute(mma_conv_kernel, cudaFuncAttributeMaxDynamicSharedMemorySize, SMEM_MMA);
        attr_done = 1;
    }

    float *actA, *actB, *stats, *nrm, *lsb;
    __half* wprep;
    cudaGetSymbolAddress((void**)&actA,  g_actA);
    cudaGetSymbolAddress((void**)&actB,  g_actB);
    cudaGetSymbolAddress((void**)&stats, g_stats);
    cudaGetSymbolAddress((void**)&nrm,   g_norm);
    cudaGetSymbolAddress((void**)&lsb,   g_loss_sb);
    cudaGetSymbolAddress((void**)&wprep, g_wprep);

    wprep_kernel<<<dim3(9, 7), 256>>>(ws);
    zero_stats_kernel<<<1, 256>>>();

    // layer 0 (1 -> 64): scalar path, stats slot 0
    conv_kernel<<<dim3(128, 4, BSZ), 256>>>(xIn, w0, b0, nullptr, actA, stats, 1);
    finalize_kernel<<<2, 256>>>(stats, nrm);

    const float* cur = actA;
    float* nxt = actB;
    for (int i = 0; i < 7; i++) {
        mma_conv_kernel<<<dim3(8, 32, BSZ), 256, SMEM_MMA>>>(
            cur, wprep + (size_t)i*18*4096, bs + i*64,
            nrm + (size_t)i*BSZ*CH*2, nxt, stats + (size_t)(i+1)*BSZ*CH*2);
        finalize_kernel<<<2, 256>>>(stats + (size_t)(i+1)*BSZ*CH*2,
                                    nrm   + (size_t)(i+1)*BSZ*CH*2);
        float* tmp = (float*)cur; cur = nxt; nxt = tmp;
    }

    proj_kernel<<<dim3(128, 1, BSZ), 256>>>(cur, nrm + (size_t)7*BSZ*CH*2,
                                            wp, bp, xIn, out);
    loss_kernel<<<dim3(169, BSZ), 256>>>(out, target, lsb);
    loss_final_kernel<<<1, 32>>>(lsb, out + (out_size - 1));
}

// round 12
// speedup vs baseline: 1.7996x; 1.0076x over previous
#include <cuda_runtime.h>
#include <cuda_fp16.h>
#include <cstdint>

#define BSZ 8
#define CH  64
#define H   256
#define W   256
#define HW  (H*W)
#define EPS 1e-5f
#define SLOPE 0.01f
#define CROP 244
#define CSPL 0.03125f   // c = 2^-5 split-compensation constant

typedef unsigned long long u64;

#define FMA2(d,a,b,c) asm("fma.rn.f32x2 %0, %1, %2, %3;" : "=l"(d) : "l"(a), "l"(b), "l"(c))
#define PACK2(d,lo,hi) asm("mov.b64 %0, {%1, %2};" : "=l"(d) : "f"(lo), "f"(hi))
#define UNPK2(lo,hi,d) asm("mov.b64 {%0, %1}, %2;" : "=f"(lo), "=f"(hi) : "l"(d))

__device__ __forceinline__ uint32_t smem_u32(const void* p) {
    uint32_t a;
    asm("{ .reg .u64 t; cvta.to.shared.u64 t, %1; cvt.u32.u64 %0, t; }" : "=r"(a) : "l"(p));
    return a;
}
__device__ __forceinline__ void ldsm4(uint32_t* r, uint32_t addr) {
    asm volatile("ldmatrix.sync.aligned.m8n8.x4.shared.b16 {%0,%1,%2,%3}, [%4];"
                 : "=r"(r[0]), "=r"(r[1]), "=r"(r[2]), "=r"(r[3]) : "r"(addr));
}
__device__ __forceinline__ void mma16816h(float* d, const uint32_t* a, const uint32_t* b) {
    asm volatile("mma.sync.aligned.m16n8k16.row.col.f32.f16.f16.f32 "
                 "{%0,%1,%2,%3}, {%4,%5,%6,%7}, {%8,%9}, {%0,%1,%2,%3};"
                 : "+f"(d[0]), "+f"(d[1]), "+f"(d[2]), "+f"(d[3])
                 : "r"(a[0]), "r"(a[1]), "r"(a[2]), "r"(a[3]), "r"(b[0]), "r"(b[1]));
}

// ---------------- scratch ----------------
__device__ float g_actA[BSZ*CH*HW];
__device__ float g_actB[BSZ*CH*HW];
__device__ float g_stats[8*BSZ*CH*2];
__device__ float g_norm[8*BSZ*CH*2];
__device__ float g_loss_part[BSZ*13*13*3];   // (X, S1hr, S2hr) per (b, sy, sx)
__device__ float g_loss_t[BSZ*2];            // (S1t, S2t) per b
// [layer][img(bh=0,b2=1)][tap][4096] fp16 ldmatrix-swizzled co x ci images
__device__ __half g_wprep[7*2*9*4096];

// ---------------- weight prep: wh image + compensated w2 image (+ zero accums) ----------------
// image layout: byte_off = co*128 + (((ci>>3) ^ (co&7))<<4) + (ci&7)*2
__global__ void wprep_kernel(const float* __restrict__ ws) {
    const int t = blockIdx.x;    // tap 0..8
    const int l = blockIdx.y;    // layer 0..6
    if (t == 0 && l == 0) {      // fold the accumulator zeroing into this launch
        for (int i = threadIdx.x; i < 8*BSZ*CH*2; i += blockDim.x) g_stats[i] = 0.f;
        for (int i = threadIdx.x; i < BSZ*13*13*3; i += blockDim.x) g_loss_part[i] = 0.f;
        if (threadIdx.x < BSZ*2) g_loss_t[threadIdx.x] = 0.f;
    }
    char* dst0 = (char*)(g_wprep + ((size_t)l*18 +     t)*4096);   // bh
    char* dst1 = (char*)(g_wprep + ((size_t)l*18 + 9 + t)*4096);   // b2
    for (int g = threadIdx.x; g < 4096; g += blockDim.x) {
        int co = g >> 6, ci = g & 63;
        float w = ws[(((size_t)l*64 + co)*64 + ci)*9 + t];
        __half wh = __float2half_rn(w);
        float whf = __half2float(wh);
        __half w2 = __float2half_rn(whf + 32.0f*(w - whf));   // wh + wl/c
        uint32_t off = (uint32_t)co*128 + ((((uint32_t)ci >> 3) ^ (co & 7)) << 4) + (ci & 7)*2;
        *(__half*)(dst0 + off) = wh;
        *(__half*)(dst1 + off) = w2;
    }
}

// ---------------- HMMA conv layer: M256 tile, sequential compensated 2-pass ----------------
// smem: window xh [340*128B], window a2 [340*128B], B dbl [2*8KB], nrm [512B]
#define OF_WHI 0
#define OF_WLO 43520
#define OF_B   87040
#define OF_NRM 103424
#define SMEM_MMA 103936
#define EPI_STRIDE 264

__global__ void __launch_bounds__(256, 2)
mma_conv_kernel(const float* __restrict__ in,
                const __half* __restrict__ wp,          // this layer: [2][9][4096]
                const float* __restrict__ bias,
                const float* __restrict__ nrm,          // [BSZ*64*2] (mean,rstd)
                float* __restrict__ out,
                float* __restrict__ statacc)            // [BSZ*64*2]
{
    extern __shared__ char smem[];
    const uint32_t sb = smem_u32(smem);
    const int tid = threadIdx.x;
    const int wid = tid >> 5, lane = tid & 31;
    const int tileW = blockIdx.x;   // 0..7   (32 w)
    const int tileH = blockIdx.y;   // 0..31  (8 h)
    const int b = blockIdx.z;

    if (tid < 64)
        *(float2*)(smem + OF_NRM + tid*8) = ((const float2*)nrm)[b*64 + tid];
    __syncthreads();   // nrm visible before window fill

    // ---- window fill: 340 rows (10h x 34w) x 64 ci ----
    for (int g = tid; g < 2720; g += 256) {
        const int chunk = g / 340;
        const int r = g - chunk*340;
        const int rr = r / 34, cc = r - rr*34;
        int gh = tileH*8 - 1 + rr; gh = gh < 0 ? 0 : (gh > H-1 ? H-1 : gh);
        int gw = tileW*32 - 1 + cc; gw = gw < 0 ? 0 : (gw > W-1 ? W-1 : gw);
        const float* src = in + ((size_t)(b*64 + chunk*8))*HW + gh*W + gw;
        unsigned short hb[8], lb[8];
        #pragma unroll
        for (int q = 0; q < 8; q++) {
            const int ci = chunk*8 + q;
            float2 mr = *(const float2*)(smem + OF_NRM + ci*8);
            float x = __ldg(src + (size_t)q*HW);
            x = (x - mr.x) * mr.y;
            x = x >= 0.f ? x : SLOPE * x;
            __half h = __float2half_rn(x);
            float xhf = __half2float(h);
            __half l = __float2half_rn((x - xhf) + CSPL*xhf);   // a2 = xl + c*xh
            hb[q] = *(unsigned short*)&h;
            lb[q] = *(unsigned short*)&l;
        }
        const uint32_t off = (uint32_t)r*128 + (uint32_t)((chunk ^ (r & 7)) << 4);
        *(uint4*)(smem + OF_WHI + off) = *(uint4*)hb;
        *(uint4*)(smem + OF_WLO + off) = *(uint4*)lb;
    }

    // ---- stage B for tt=0 (bh, tap 0) into buffer 0 ----
    const uint4* wp4 = (const uint4*)wp;   // [18][512] uint4
    *(uint4*)(smem + OF_B + (uint32_t)tid*16)         = __ldg(wp4 + tid);
    *(uint4*)(smem + OF_B + (uint32_t)(tid + 256)*16) = __ldg(wp4 + tid + 256);
    __syncthreads();

    // warp geometry: 4 M-strips (64 px = two h-rows) x 2 N-halves (32 co)
    const int mwid = wid >> 1;           // 0..3
    const int nwid = wid & 1;            // 0..1
    const int gA  = lane >> 3;
    const int rl  = (lane & 7) + (gA & 1)*8;
    const int aK  = gA >> 1;
    const int bRow = (lane & 7) + ((lane >> 4) & 1)*8;
    const int bK   = (lane >> 3) & 1;
    const int bsw  = lane & 7;

    float d[4][4][4];   // [mf][n8][frag]
    #pragma unroll
    for (int mf = 0; mf < 4; mf++)
        #pragma unroll
        for (int n = 0; n < 4; n++)
            #pragma unroll
            for (int j = 0; j < 4; j++) d[mf][n][j] = 0.f;

    #pragma unroll 1
    for (int tt = 0; tt < 18; tt++) {
        // prefetch next stage's B image tap
        uint4 pre0, pre1;
        if (tt < 17) {
            const uint4* np = wp4 + (size_t)(tt + 1)*512;
            pre0 = __ldg(np + tid);
            pre1 = __ldg(np + tid + 256);
        }

        // between passes: d *= (1 - c)  (exactly once, after all pass-1 MMAs)
        if (tt == 9) {
            #pragma unroll
            for (int mf = 0; mf < 4; mf++)
                #pragma unroll
                for (int n = 0; n < 4; n++)
                    #pragma unroll
                    for (int j = 0; j < 4; j++) d[mf][n][j] *= (1.0f - CSPL);
        }

        const int t  = tt < 9 ? tt : tt - 9;
        const int kh = t / 3, kw = t - kh*3;
        const uint32_t aBase = sb + (tt < 9 ? OF_WHI : OF_WLO);
        int wr[4];
        #pragma unroll
        for (int mf = 0; mf < 4; mf++) {
            const int hh = mwid*2 + (mf >> 1);
            wr[mf] = (hh + kh)*34 + (mf & 1)*16 + kw + rl;
        }
        const uint32_t bB = sb + OF_B + (uint32_t)(tt & 1)*8192;

        #pragma unroll
        for (int ks = 0; ks < 4; ks++) {
            uint32_t a[4][4];
            #pragma unroll
            for (int mf = 0; mf < 4; mf++)
                ldsm4(a[mf], aBase + (uint32_t)wr[mf]*128
                              + (uint32_t)(((2*ks + aK) ^ (wr[mf] & 7)) << 4));
            uint32_t bf[2][4];
            const uint32_t cb = (uint32_t)(((2*ks + bK) ^ bsw) << 4);
            #pragma unroll
            for (int nn = 0; nn < 2; nn++)
                ldsm4(bf[nn], bB + (uint32_t)((nwid*2 + nn)*16 + bRow)*128 + cb);
            #pragma unroll
            for (int mf = 0; mf < 4; mf++)
                #pragma unroll
                for (int n = 0; n < 4; n++)
                    mma16816h(d[mf][n], a[mf], &bf[n >> 1][(n & 1)*2]);
        }

        if (tt < 17) {
            char* dst = smem + OF_B + (uint32_t)((tt + 1) & 1)*8192;
            *(uint4*)(dst + (uint32_t)tid*16)         = pre0;
            *(uint4*)(dst + (uint32_t)(tid + 256)*16) = pre1;
            __syncthreads();
        }
    }

    // ---- epilogue: d -> smem (stride 264) -> coalesced store + fused stats ----
    __syncthreads();   // window reads done; safe to overwrite
    float* epi = (float*)smem;
    #pragma unroll
    for (int mf = 0; mf < 4; mf++)
        #pragma unroll
        for (int n = 0; n < 4; n++)
            #pragma unroll
            for (int j = 0; j < 4; j++) {
                const int r16 = (lane >> 2) + ((j >> 1) << 3);
                const int px = (mwid*2 + (mf >> 1))*32 + (mf & 1)*16 + r16;
                const int co = nwid*32 + n*8 + (lane & 3)*2 + (j & 1);
                epi[co*EPI_STRIDE + px] = d[mf][n][j];
            }
    __syncthreads();

    {
        const int h0 = tileH*8, w0 = tileW*32;
        #pragma unroll 1
        for (int k = 0; k < 8; k++) {
            const int co = wid*8 + k;
            const float bv = __ldg(bias + co);
            float* op = out + ((size_t)(b*64 + co))*HW + (size_t)h0*W + w0;
            float s = 0.f, q = 0.f;
            #pragma unroll
            for (int i = 0; i < 8; i++) {
                float v = epi[co*EPI_STRIDE + i*32 + lane] + bv;
                op[(size_t)i*W + lane] = v;
                s += v; q += v*v;
            }
            #pragma unroll
            for (int off = 16; off; off >>= 1) {
                s += __shfl_down_sync(0xffffffffu, s, off);
                q += __shfl_down_sync(0xffffffffu, q, off);
            }
            if (lane == 0) {
                atomicAdd(&statacc[(b*64 + co)*2    ], s);
                atomicAdd(&statacc[(b*64 + co)*2 + 1], q);
            }
        }
    }
}

// ---------------- stats -> (mean, rstd) ----------------
__global__ void finalize_kernel(const float* __restrict__ acc, float* __restrict__ nrm) {
    int i = blockIdx.x * blockDim.x + threadIdx.x;
    if (i < BSZ*CH) {
        const float inv = 1.f / (float)HW;
        float m = acc[2*i] * inv;
        float v = acc[2*i + 1] * inv - m*m;
        nrm[2*i]     = m;
        nrm[2*i + 1] = rsqrtf(v + EPS);
    }
}

// ---------------- layer-0 scalar conv (cin=1, proven) ----------------
__global__ __launch_bounds__(256, 2)
void conv_kernel(const float* __restrict__ in,
                 const float* __restrict__ wgt,
                 const float* __restrict__ bias,
                 const float* __restrict__ innorm,
                 float* __restrict__ out,
                 float* __restrict__ statacc,
                 int cin)
{
    __shared__ float s_w[64*9*16];
    __shared__ float s_in[2][18*36];

    const int tid   = threadIdx.x;
    const int tileW = blockIdx.x & 7;
    const int tileH = blockIdx.x >> 3;
    const int co_base = blockIdx.y * 16;
    const int b = blockIdx.z;

    const int nw = cin * 9 * 16;
    for (int g = tid; g < nw; g += 256) {
        int co_l = g & 15;
        int ct   = g >> 4;
        int ci   = ct / 9;
        int t    = ct - ci*9;
        s_w[g] = wgt[((co_base + co_l)*cin + ci)*9 + t];
    }

    const int sp = tid & 63, cg = tid >> 6;
    const int ph = sp >> 3, pw = sp & 7;
    const int h0 = tileH*16 + ph*2;
    const int w0 = tileW*32 + pw*4;
    const int hbase = tileH*16 - 1, wbase = tileW*32 - 1;

    int srcO[3], dstO[3]; bool act[3];
    #pragma unroll
    for (int k = 0; k < 3; k++) {
        int g = tid + k*256;
        act[k] = (g < 612);
        int gg = act[k] ? g : 0;
        int r = gg / 34, c = gg - r * 34;
        int gh = hbase + r; gh = gh < 0 ? 0 : (gh > H-1 ? H-1 : gh);
        int gw = wbase + c; gw = gw < 0 ? 0 : (gw > W-1 ? W-1 : gw);
        srcO[k] = gh*W + gw;
        dstO[k] = r*36 + c;
    }

    const float* inb = in + (size_t)b * cin * HW;

    {
        float mean = 0.f, rstd = 1.f;
        if (innorm) { mean = innorm[(b*cin)*2]; rstd = innorm[(b*cin)*2+1]; }
        #pragma unroll
        for (int k = 0; k < 3; k++) if (act[k]) {
            float v = inb[srcO[k]];
            if (innorm) { v = (v - mean) * rstd; v = v >= 0.f ? v : SLOPE * v; }
            s_in[0][dstO[k]] = v;
        }
    }
    __syncthreads();

    u64 acc[2][2][4];
    #pragma unroll
    for (int p = 0; p < 2; p++)
        #pragma unroll
        for (int i = 0; i < 2; i++)
            #pragma unroll
            for (int j = 0; j < 4; j++) acc[p][i][j] = 0ull;

    for (int ci = 0; ci < cin; ci++) {
        const int buf = ci & 1;
        const int cn = (ci + 1 < cin) ? ci + 1 : cin - 1;

        float pre[3];
        float nmean = 0.f, nrstd = 1.f;
        {
            const float* pn = inb + (size_t)cn * HW;
            if (innorm) {
                nmean = innorm[(b*cin + cn)*2];
                nrstd = innorm[(b*cin + cn)*2 + 1];
            }
            #pragma unroll
            for (int k = 0; k < 3; k++) pre[k] = act[k] ? pn[srcO[k]] : 0.f;
        }

        u64 dup[4][6];
        #pragma unroll
        for (int r = 0; r < 4; r++) {
            const float* row = &s_in[buf][(ph*2 + r)*36 + pw*4];
            float4 v4 = *reinterpret_cast<const float4*>(row);
            float2 v2 = *reinterpret_cast<const float2*>(row + 4);
            PACK2(dup[r][0], v4.x, v4.x);
            PACK2(dup[r][1], v4.y, v4.y);
            PACK2(dup[r][2], v4.z, v4.z);
            PACK2(dup[r][3], v4.w, v4.w);
            PACK2(dup[r][4], v2.x, v2.x);
            PACK2(dup[r][5], v2.y, v2.y);
        }

        const float* wrow = &s_w[ci*9*16 + cg*4];
        #pragma unroll
        for (int p = 0; p < 2; p++) {
            u64 wv[9];
            #pragma unroll
            for (int t = 0; t < 9; t++)
                wv[t] = *reinterpret_cast<const u64*>(&wrow[t*16 + p*2]);
            #pragma unroll
            for (int kh = 0; kh < 3; kh++)
                #pragma unroll
                for (int kw = 0; kw < 3; kw++)
                    #pragma unroll
                    for (int i = 0; i < 2; i++)
                        #pragma unroll
                        for (int j = 0; j < 4; j++)
                            FMA2(acc[p][i][j], dup[i+kh][j+kw], wv[kh*3+kw], acc[p][i][j]);
        }

        #pragma unroll
        for (int k = 0; k < 3; k++) if (act[k]) {
            float v = pre[k];
            if (innorm) { v = (v - nmean) * nrstd; v = v >= 0.f ? v : SLOPE * v; }
            s_in[buf ^ 1][dstO[k]] = v;
        }
        __syncthreads();
    }

    #pragma unroll
    for (int p = 0; p < 2; p++) {
        const int co0 = co_base + cg*4 + 2*p;
        const float bv0 = bias[co0], bv1 = bias[co0 + 1];
        float* ob0 = out + (size_t)(b*CH + co0    ) * HW;
        float* ob1 = out + (size_t)(b*CH + co0 + 1) * HW;
        float s0 = 0.f, q0 = 0.f, s1 = 0.f, q1 = 0.f;
        #pragma unroll
        for (int i = 0; i < 2; i++) {
            float lo[4], hi[4];
            #pragma unroll
            for (int j = 0; j < 4; j++) {
                float l, h2;
                UNPK2(l, h2, acc[p][i][j]);
                lo[j] = l + bv0; hi[j] = h2 + bv1;
                s0 += lo[j]; q0 += lo[j]*lo[j];
                s1 += hi[j]; q1 += hi[j]*hi[j];
            }
            *reinterpret_cast<float4*>(&ob0[(h0+i)*W + w0]) = make_float4(lo[0],lo[1],lo[2],lo[3]);
            *reinterpret_cast<float4*>(&ob1[(h0+i)*W + w0]) = make_float4(hi[0],hi[1],hi[2],hi[3]);
        }
        #pragma unroll
        for (int off = 16; off; off >>= 1) {
            s0 += __shfl_down_sync(0xffffffffu, s0, off);
            q0 += __shfl_down_sync(0xffffffffu, q0, off);
            s1 += __shfl_down_sync(0xffffffffu, s1, off);
            q1 += __shfl_down_sync(0xffffffffu, q1, off);
        }
        if ((tid & 31) == 0) {
            atomicAdd(&statacc[(b*CH + co0)*2    ], s0);
            atomicAdd(&statacc[(b*CH + co0)*2 + 1], q0);
            atomicAdd(&statacc[(b*CH + co0+1)*2    ], s1);
            atomicAdd(&statacc[(b*CH + co0+1)*2 + 1], q1);
        }
    }
}

// ---------------- projection conv (64->1) + residual: 16x32 tile, dbl-buffered ----------------
__global__ __launch_bounds__(256)
void proj_kernel(const float* __restrict__ in, const float* __restrict__ innorm,
                 const float* __restrict__ wgt, const float* __restrict__ bias,
                 const float* __restrict__ xIn, float* __restrict__ out)
{
    __shared__ float s_w[64*9];
    __shared__ float s_in[2][18*36];
    const int tid = threadIdx.x;
    const int tileW = blockIdx.x & 7;
    const int tileH = blockIdx.x >> 3;   // 0..15
    const int b = blockIdx.z;

    for (int g = tid; g < 576; g += 256) s_w[g] = wgt[g];

    const int pw = tid & 31, hp = tid >> 5;  // w 0..31, hpair 0..7
    const int h0 = tileH*16 + hp*2;
    const int w0 = tileW*32 + pw;
    const int hbase = tileH*16 - 1, wbase = tileW*32 - 1;

    int srcO[3], dstO[3]; bool act[3];
    #pragma unroll
    for (int k = 0; k < 3; k++) {
        int g = tid + k*256;
        act[k] = (g < 612);
        int gg = act[k] ? g : 0;
        int r = gg / 34, c = gg - r*34;
        int gh = hbase + r; gh = gh < 0 ? 0 : (gh > H-1 ? H-1 : gh);
        int gw = wbase + c; gw = gw < 0 ? 0 : (gw > W-1 ? W-1 : gw);
        srcO[k] = gh*W + gw;
        dstO[k] = r*36 + c;
    }

    const float* inb = in + (size_t)b*64*HW;
    const float2* nrmb = (const float2*)innorm + b*64;

    {
        float2 mr = nrmb[0];
        #pragma unroll
        for (int k = 0; k < 3; k++) if (act[k]) {
            float v = inb[srcO[k]];
            v = (v - mr.x) * mr.y;
            v = v >= 0.f ? v : SLOPE * v;
            s_in[0][dstO[k]] = v;
        }
    }
    __syncthreads();

    float acc0 = 0.f, acc1 = 0.f;
    for (int ci = 0; ci < 64; ci++) {
        const int buf = ci & 1;
        const int cn = (ci + 1 < 64) ? ci + 1 : 63;
        float pre[3];
        float2 nmr = nrmb[cn];
        {
            const float* pn = inb + (size_t)cn*HW;
            #pragma unroll
            for (int k = 0; k < 3; k++) pre[k] = act[k] ? pn[srcO[k]] : 0.f;
        }

        float rr[4][3];
        #pragma unroll
        for (int r = 0; r < 4; r++)
            #pragma unroll
            for (int c = 0; c < 3; c++)
                rr[r][c] = s_in[buf][(hp*2 + r)*36 + pw + c];

        const float* wv = &s_w[ci*9];
        #pragma unroll
        for (int kh = 0; kh < 3; kh++)
            #pragma unroll
            for (int kw = 0; kw < 3; kw++) {
                float wvv = wv[kh*3 + kw];
                acc0 = fmaf(rr[kh    ][kw], wvv, acc0);
                acc1 = fmaf(rr[kh + 1][kw], wvv, acc1);
            }

        #pragma unroll
        for (int k = 0; k < 3; k++) if (act[k]) {
            float v = pre[k];
            v = (v - nmr.x) * nmr.y;
            v = v >= 0.f ? v : SLOPE * v;
            s_in[buf ^ 1][dstO[k]] = v;
        }
        __syncthreads();
    }

    int idx = b*HW + h0*W + w0;
    out[idx]     = acc0 + bias[0] + xIn[idx];
    out[idx + W] = acc1 + bias[0] + xIn[idx + W];
}

// ---------------- shift-search loss: streaming partials ----------------
// block (sy, rchunk, b): 61 hr rows + t rows, 13 sx accumulated in registers
__global__ __launch_bounds__(256)
void loss_part_kernel(const float* __restrict__ hr, const float* __restrict__ tgt)
{
    const int sy = blockIdx.x, rc = blockIdx.y, b = blockIdx.z;
    const int tid = threadIdx.x;
    const int lane = tid & 31;
    __shared__ float s_hr[2][256];
    __shared__ float s_t[2][244];

    const float* hp = hr  + (size_t)b*HW;
    const float* tp = tgt + (size_t)b*HW;
    const int r0 = rc*61;

    float X[13], S1[13], S2[13];
    #pragma unroll
    for (int s = 0; s < 13; s++) { X[s] = 0.f; S1[s] = 0.f; S2[s] = 0.f; }
    float t1 = 0.f, t2 = 0.f;

    // preload row r0 into buffer 0
    s_hr[0][tid] = hp[(sy + r0)*W + tid];
    if (tid < CROP) s_t[0][tid] = tp[(6 + r0)*W + 6 + tid];
    __syncthreads();

    for (int r = 0; r < 61; r++) {
        const int buf = r & 1;
        float hv = 0.f, tv = 0.f;
        if (r < 60) {
            hv = hp[(sy + r0 + r + 1)*W + tid];
            if (tid < CROP) tv = tp[(6 + r0 + r + 1)*W + 6 + tid];
        }
        if (tid < CROP) {
            const float tc = s_t[buf][tid];
            t1 += tc; t2 = fmaf(tc, tc, t2);
            #pragma unroll
            for (int s = 0; s < 13; s++) {
                const float v = s_hr[buf][s + tid];
                X[s]  = fmaf(v, tc, X[s]);
                S1[s] += v;
                S2[s] = fmaf(v, v, S2[s]);
            }
        }
        if (r < 60) {
            s_hr[buf ^ 1][tid] = hv;
            if (tid < CROP) s_t[buf ^ 1][tid] = tv;
        }
        __syncthreads();
    }

    float* part = g_loss_part + ((size_t)(b*13 + sy))*13*3;
    #pragma unroll
    for (int s = 0; s < 13; s++) {
        float x = X[s], a = S1[s], q = S2[s];
        #pragma unroll
        for (int off = 16; off; off >>= 1) {
            x += __shfl_down_sync(0xffffffffu, x, off);
            a += __shfl_down_sync(0xffffffffu, a, off);
            q += __shfl_down_sync(0xffffffffu, q, off);
        }
        if (lane == 0) {
            atomicAdd(&part[s*3    ], x);
            atomicAdd(&part[s*3 + 1], a);
            atomicAdd(&part[s*3 + 2], q);
        }
    }
    if (sy == 0) {
        #pragma unroll
        for (int off = 16; off; off >>= 1) {
            t1 += __shfl_down_sync(0xffffffffu, t1, off);
            t2 += __shfl_down_sync(0xffffffffu, t2, off);
        }
        if (lane == 0) {
            atomicAdd(&g_loss_t[b*2    ], t1);
            atomicAdd(&g_loss_t[b*2 + 1], t2);
        }
    }
}

__global__ __launch_bounds__(256)
void loss_final_kernel(float* __restrict__ outp) {
    __shared__ float mn[256];
    const float invN = 1.f / ((float)CROP * (float)CROP);
    float total = 0.f;
    for (int b = 0; b < BSZ; b++) {
        float v = 1e30f;
        if (threadIdx.x < 169) {
            const float* part = g_loss_part + ((size_t)b*169 + threadIdx.x)*3;
            const float Xv = part[0], S1 = part[1], S2 = part[2];
            const float T1 = g_loss_t[b*2], T2 = g_loss_t[b*2 + 1];
            const float e2 = (S2 - 2.f*Xv + T2) * invN;
            const float e1 = (S1 - T1) * invN;
            v = e2 - e1*e1;
        }
        mn[threadIdx.x] = v;
        __syncthreads();
        for (int off = 128; off; off >>= 1) {
            if (threadIdx.x < off) mn[threadIdx.x] = fminf(mn[threadIdx.x], mn[threadIdx.x + off]);
            __syncthreads();
        }
        if (threadIdx.x == 0) total += mn[0];
        __syncthreads();
    }
    if (threadIdx.x == 0) outp[0] = total * (1.f / BSZ);
}

// ---------------- launch ----------------
extern "C" void kernel_launch(void* const* d_in, const int* in_sizes, int n_in,
                              void* d_out, int out_size)
{
    const float* xIn    = (const float*)d_in[0];
    const float* target = (const float*)d_in[1];
    const float* w0     = (const float*)d_in[2];
    const float* b0     = (const float*)d_in[3];
    const float* ws     = (const float*)d_in[4];
    const float* bs     = (const float*)d_in[5];
    const float* wp     = (const float*)d_in[6];
    const float* bp     = (const float*)d_in[7];
    float* out = (float*)d_out;

    static int attr_done = 0;
    if (!attr_done) {
        cudaFuncSetAttribute(mma_conv_kernel, cudaFuncAttributeMaxDynamicSharedMemorySize, SMEM_MMA);
        attr_done = 1;
    }

    float *actA, *actB, *stats, *nrm;
    __half* wprep;
    cudaGetSymbolAddress((void**)&actA,  g_actA);
    cudaGetSymbolAddress((void**)&actB,  g_actB);
    cudaGetSymbolAddress((void**)&stats, g_stats);
    cudaGetSymbolAddress((void**)&nrm,   g_norm);
    cudaGetSymbolAddress((void**)&wprep, g_wprep);

    // launch 1: weight prep + accumulator zeroing
    wprep_kernel<<<dim3(9, 7), 256>>>(ws);

    // launch 2-3: layer 0 (1 -> 64) scalar path, stats slot 0
    conv_kernel<<<dim3(128, 4, BSZ), 256>>>(xIn, w0, b0, nullptr, actA, stats, 1);
    finalize_kernel<<<2, 256>>>(stats, nrm);

    const float* cur = actA;
    float* nxt = actB;
    for (int i = 0; i < 7; i++) {
        mma_conv_kernel<<<dim3(8, 32, BSZ), 256, SMEM_MMA>>>(
            cur, wprep + (size_t)i*18*4096, bs + i*64,
            nrm + (size_t)i*BSZ*CH*2, nxt, stats + (size_t)(i+1)*BSZ*CH*2);
        finalize_kernel<<<2, 256>>>(stats + (size_t)(i+1)*BSZ*CH*2,
                                    nrm   + (size_t)(i+1)*BSZ*CH*2);
        float* tmp = (float*)cur; cur = nxt; nxt = tmp;
    }

    proj_kernel<<<dim3(128, 1, BSZ), 256>>>(cur, nrm + (size_t)7*BSZ*CH*2,
                                            wp, bp, xIn, out);
    loss_part_kernel<<<dim3(13, 4, BSZ), 256>>>(out, target);
    loss_final_kernel<<<1, 256>>>(out + (out_size - 1));
}